// round 15
// baseline (speedup 1.0000x reference)
#include <cuda_runtime.h>
#include <cuda_fp16.h>
#include <cstdint>

// Problem constants
#define NN   20000
#define EE   640000
#define F0   128
#define F1   256
#define F2   128
#define NPAD 20096   // 157 * 128
#define MAXD 128     // ELL slots per node

// ---------------- scratch (device globals, zero at module load) -------------
__device__ __align__(16) unsigned g_degcnt[2 * NPAD];   // deg(float) | cnt(int)
__device__ __align__(16) int2   g_pack[NPAD * MAXD];    // ELL: (src_row, w) per dst
__device__ __align__(16) __half g_TxA[4 * NPAD * F0];
__device__ __align__(16) __half g_out1[NPAD * F1];
__device__ __align__(16) __half g_Ck[4 * NPAD * F2];
__device__ __align__(16) __half g_out2[NPAD * F2];
__device__ __align__(16) __half g_W1h[4 * F0 * F1];
__device__ __align__(16) __half g_W2h[4 * F1 * F2];
__device__ __align__(16) float  g_bias2[4 * F2];
__device__ __align__(16) float  g_stats[2 * F1];
__device__ __align__(16) float  g_stats2[2 * F2];

// ---------------- ELL build: single edge pass --------------------------------
__global__ void pass1_kernel(const int* __restrict__ row,
                             const int* __restrict__ col,
                             const float* __restrict__ ew) {
    int e = blockIdx.x * blockDim.x + threadIdx.x;
    if (e >= EE) return;
    int r = row[e], c = col[e];
    float w = (r == c) ? 0.f : ew[e];
    float* deg = (float*)g_degcnt;
    int*   cnt = (int*)(g_degcnt + NPAD);
    if (w != 0.f) atomicAdd(&deg[r], w);
    int slot = atomicAdd(&cnt[c], 1);
    int2 p;
    p.x = r;
    p.y = __float_as_int(w);
    g_pack[c * MAXD + slot] = p;
}

// transform: wn = -rsqrt(deg[r]) * w * rsqrt(deg[c]) in-place; zero stat buffers
__global__ void transform_kernel() {
    int tid = threadIdx.x;
    if (blockIdx.x == 0) {
        for (int i = tid; i < 2 * F1; i += 256) g_stats[i] = 0.f;
        for (int i = tid; i < 2 * F2; i += 256) g_stats2[i] = 0.f;
        for (int i = tid; i < 4 * F2; i += 256) g_bias2[i] = 0.f;
    }
    int node = (blockIdx.x * blockDim.x + tid) >> 5;
    if (node >= NN) return;
    int lane = tid & 31;
    const float* deg = (const float*)g_degcnt;
    const int*   cnt = (const int*)(g_degcnt + NPAD);
    float dc = deg[node];
    float disc = (dc > 0.f) ? rsqrtf(dc) : 0.f;
    int n = cnt[node];
    int base = node * MAXD;
    for (int i = lane; i < n; i += 32) {
        int2 p = g_pack[base + i];
        float w = __int_as_float(p.y);
        float dr = deg[p.x];
        float disr = (dr > 0.f) ? rsqrtf(dr) : 0.f;
        p.y = __float_as_int(-disr * w * disc);
        g_pack[base + i] = p;
    }
}

// merged converts: x -> TxA block 0, W1 -> W1h
#define XCNT (NN * 32)
#define WCNT (4 * F0 * F1 / 4)
__global__ void cvt_kernel(const float* __restrict__ x, const float* __restrict__ W1) {
    int i = blockIdx.x * blockDim.x + threadIdx.x;
    if (i >= XCNT + WCNT) return;
    const float4* src;
    uint2* dst;
    if (i < XCNT) {
        src = (const float4*)x + i;
        dst = (uint2*)g_TxA + i;
    } else {
        src = (const float4*)W1 + (i - XCNT);
        dst = (uint2*)g_W1h + (i - XCNT);
    }
    float4 v = *src;
    uint2 o;
    __half2 h0 = __floats2half2_rn(v.x, v.y);
    __half2 h1 = __floats2half2_rn(v.z, v.w);
    o.x = *(unsigned*)&h0;
    o.y = *(unsigned*)&h1;
    *dst = o;
}

// ---- gather SPMM (fp16, F=128): out = alpha*(L@in) - sub + add --------------
// Shuffles distribute edge metadata; 16 gathers in flight.
__device__ __forceinline__ void hfma4(float4& acc, float w, uint2 u) {
    float2 f0 = __half22float2(*(__half2*)&u.x);
    float2 f1 = __half22float2(*(__half2*)&u.y);
    acc.x = fmaf(w, f0.x, acc.x);
    acc.y = fmaf(w, f0.y, acc.y);
    acc.z = fmaf(w, f1.x, acc.z);
    acc.w = fmaf(w, f1.y, acc.w);
}

__global__ void spmm_h(const __half* __restrict__ in, __half* __restrict__ out,
                       const __half* __restrict__ sub,
                       const __half* __restrict__ add, float alpha) {
    int node = (blockIdx.x * blockDim.x + threadIdx.x) >> 5;
    if (node >= NN) return;
    int lane = threadIdx.x & 31;
    int n = ((const int*)(g_degcnt + NPAD))[node];
    const int2* pk = g_pack + node * MAXD;
    const uint2* base = (const uint2*)in + lane;

    float4 acc[4];
#pragma unroll
    for (int i = 0; i < 4; ++i) acc[i] = make_float4(0.f, 0.f, 0.f, 0.f);

    for (int c0 = 0; c0 < n; c0 += 32) {
        int m = n - c0;
        if (m > 32) m = 32;
        // coalesced pack load; inactive lanes padded with (row=0, w=0)
        int2 p = (lane < m) ? pk[c0 + lane] : make_int2(0, 0);
        int mm = (m + 15) & ~15;   // round up to 16; padded edges harmless (w=0)
#pragma unroll 1
        for (int j = 0; j < mm; j += 16) {
            int rr[16];
            uint2 uu[16];
            float ww[16];
#pragma unroll
            for (int t = 0; t < 16; ++t)
                rr[t] = __shfl_sync(0xffffffffu, p.x, j + t);
#pragma unroll
            for (int t = 0; t < 16; ++t)
                uu[t] = base[(size_t)rr[t] * 32];
#pragma unroll
            for (int t = 0; t < 16; ++t)
                ww[t] = __int_as_float(__shfl_sync(0xffffffffu, p.y, j + t));
#pragma unroll
            for (int t = 0; t < 16; ++t)
                hfma4(acc[t & 3], ww[t], uu[t]);
        }
    }
    float4 r;
    r.x = alpha * ((acc[0].x + acc[1].x) + (acc[2].x + acc[3].x));
    r.y = alpha * ((acc[0].y + acc[1].y) + (acc[2].y + acc[3].y));
    r.z = alpha * ((acc[0].z + acc[1].z) + (acc[2].z + acc[3].z));
    r.w = alpha * ((acc[0].w + acc[1].w) + (acc[2].w + acc[3].w));
    size_t oidx = (size_t)node * 32 + lane;
    if (add) {
        uint2 u = ((const uint2*)add)[oidx];
        float2 f0 = __half22float2(*(__half2*)&u.x);
        float2 f1 = __half22float2(*(__half2*)&u.y);
        r.x += f0.x; r.y += f0.y; r.z += f1.x; r.w += f1.y;
    }
    if (sub) {
        uint2 u = ((const uint2*)sub)[oidx];
        float2 f0 = __half22float2(*(__half2*)&u.x);
        float2 f1 = __half22float2(*(__half2*)&u.y);
        r.x -= f0.x; r.y -= f0.y; r.z -= f1.x; r.w -= f1.y;
    }
    uint2 o;
    __half2 h0 = __floats2half2_rn(r.x, r.y);
    __half2 h1 = __floats2half2_rn(r.z, r.w);
    o.x = *(unsigned*)&h0;
    o.y = *(unsigned*)&h1;
    ((uint2*)out)[oidx] = o;
}

// ---------------- fp16 tensor-core GEMMs, cp.async double-buffered -----------
#define PA 40
#define PB 136
#define ASTG (128 * PA)
#define BSTG (32 * PB)

__device__ __forceinline__ void cp16(unsigned sdst, const void* gsrc) {
    asm volatile("cp.async.cg.shared.global [%0], [%1], 16;" :: "r"(sdst), "l"(gsrc));
}

// GEMM1: out1(h) = relu( sum_chunk TxA_chunk @ W1h_chunk + b1 ) ; fused BN1 stats
__global__ __launch_bounds__(256)
void gemm1_f16(const __half* __restrict__ A, const float* __restrict__ bias,
               __half* __restrict__ C) {
    __shared__ __align__(16) __half As[2 * ASTG];
    __shared__ __align__(16) __half Bs[2 * BSTG];
    __shared__ float sS[128], sQ[128];

    const int tid = threadIdx.x;
    const int lane = tid & 31;
    const int wid = tid >> 5;
    const int warp_m = wid >> 2;
    const int warp_n = wid & 3;
    const int bm = blockIdx.x * 128;
    const int bn = blockIdx.y * 128;
    const int NIT = 16;

    if (tid < 128) { sS[tid] = 0.f; sQ[tid] = 0.f; }

    float acc[4][4][4];
#pragma unroll
    for (int i = 0; i < 4; i++)
#pragma unroll
        for (int j = 0; j < 4; j++)
#pragma unroll
            for (int q = 0; q < 4; q++) acc[i][j][q] = 0.f;

    const unsigned asBase0 = (unsigned)__cvta_generic_to_shared(As);
    const unsigned bsBase0 = (unsigned)__cvta_generic_to_shared(Bs);
    const unsigned asFrag = asBase0 +
        ((warp_m * 64 + (lane & 15)) * PA + (lane >> 4) * 8) * 2;
    const int b_k = ((lane >> 3) & 1) * 8 + (lane & 7);
    const int b_n = (lane >> 4) * 8;

    auto load_tiles = [&](int st, int it) {
        int chunk = it >> 2;
        int k0 = (it & 3) * 32;
        const __half* Ab = A + (size_t)chunk * NPAD * F0 + (size_t)bm * F0 + k0;
        const __half* Wb = g_W1h + (size_t)chunk * F0 * F1 + (size_t)k0 * F1 + bn;
        unsigned sA = asBase0 + st * ASTG * 2;
        unsigned sB = bsBase0 + st * BSTG * 2;
#pragma unroll
        for (int p = 0; p < 2; ++p) {
            int idx = p * 256 + tid;
            int rrow = idx >> 2, ch = (idx & 3) * 8;
            cp16(sA + (rrow * PA + ch) * 2, Ab + (size_t)rrow * F0 + ch);
            int kr = idx >> 4, bc = (idx & 15) * 8;
            cp16(sB + (kr * PB + bc) * 2, Wb + (size_t)kr * F1 + bc);
        }
        asm volatile("cp.async.commit_group;");
    };

    load_tiles(0, 0);
    int st = 0;
#pragma unroll 1
    for (int it = 0; it < NIT; ++it) {
        if (it + 1 < NIT) {
            load_tiles(st ^ 1, it + 1);
            asm volatile("cp.async.wait_group 1;");
        } else {
            asm volatile("cp.async.wait_group 0;");
        }
        __syncthreads();
#pragma unroll
        for (int ks = 0; ks < 2; ++ks) {
            unsigned a[4][4];
#pragma unroll
            for (int ms = 0; ms < 4; ++ms) {
                unsigned addr = asFrag + st * ASTG * 2 + ms * (16 * PA * 2) + ks * 32;
                asm volatile(
                    "ldmatrix.sync.aligned.m8n8.x4.shared.b16 {%0,%1,%2,%3}, [%4];"
                    : "=r"(a[ms][0]), "=r"(a[ms][1]), "=r"(a[ms][2]), "=r"(a[ms][3])
                    : "r"(addr));
            }
            unsigned b[4][2];
#pragma unroll
            for (int nsp = 0; nsp < 2; ++nsp) {
                int ncol = warp_n * 32 + nsp * 16 + b_n;
                unsigned baddr = bsBase0 + st * BSTG * 2 +
                                 ((ks * 16 + b_k) * PB + ncol) * 2;
                asm volatile(
                    "ldmatrix.sync.aligned.m8n8.x4.trans.shared.b16 {%0,%1,%2,%3}, [%4];"
                    : "=r"(b[2 * nsp][0]), "=r"(b[2 * nsp][1]),
                      "=r"(b[2 * nsp + 1][0]), "=r"(b[2 * nsp + 1][1])
                    : "r"(baddr));
            }
#pragma unroll
            for (int ms = 0; ms < 4; ++ms)
#pragma unroll
                for (int ns = 0; ns < 4; ++ns) {
                    asm volatile(
                        "mma.sync.aligned.m16n8k16.row.col.f32.f16.f16.f32 "
                        "{%0,%1,%2,%3}, {%4,%5,%6,%7}, {%8,%9}, {%0,%1,%2,%3};"
                        : "+f"(acc[ms][ns][0]), "+f"(acc[ms][ns][1]),
                          "+f"(acc[ms][ns][2]), "+f"(acc[ms][ns][3])
                        : "r"(a[ms][0]), "r"(a[ms][1]), "r"(a[ms][2]), "r"(a[ms][3]),
                          "r"(b[ns][0]), "r"(b[ns][1]));
                }
        }
        __syncthreads();
        st ^= 1;
    }

    float s[4][2], q[4][2];
#pragma unroll
    for (int ns = 0; ns < 4; ++ns) { s[ns][0] = s[ns][1] = q[ns][0] = q[ns][1] = 0.f; }
#pragma unroll
    for (int ms = 0; ms < 4; ++ms) {
        int r0 = bm + warp_m * 64 + ms * 16 + (lane >> 2);
        bool ok0 = r0 < NN, ok1 = (r0 + 8) < NN;
#pragma unroll
        for (int ns = 0; ns < 4; ++ns) {
            int cc = bn + warp_n * 32 + ns * 8 + 2 * (lane & 3);
            float a0 = fmaxf(acc[ms][ns][0] + bias[cc + 0], 0.f);
            float a1 = fmaxf(acc[ms][ns][1] + bias[cc + 1], 0.f);
            float a2 = fmaxf(acc[ms][ns][2] + bias[cc + 0], 0.f);
            float a3 = fmaxf(acc[ms][ns][3] + bias[cc + 1], 0.f);
            __half2 h0 = __floats2half2_rn(a0, a1);
            __half2 h1 = __floats2half2_rn(a2, a3);
            *(__half2*)&C[(size_t)r0 * F1 + cc] = h0;
            *(__half2*)&C[(size_t)(r0 + 8) * F1 + cc] = h1;
            float m0 = ok0 ? a0 : 0.f;
            float m1 = ok0 ? a1 : 0.f;
            float m2 = ok1 ? a2 : 0.f;
            float m3 = ok1 ? a3 : 0.f;
            s[ns][0] += m0 + m2;
            s[ns][1] += m1 + m3;
            q[ns][0] += m0 * m0 + m2 * m2;
            q[ns][1] += m1 * m1 + m3 * m3;
        }
    }
#pragma unroll
    for (int ns = 0; ns < 4; ++ns)
#pragma unroll
        for (int par = 0; par < 2; ++par) {
            float sv = s[ns][par], qv = q[ns][par];
            sv += __shfl_xor_sync(0xffffffffu, sv, 4);
            sv += __shfl_xor_sync(0xffffffffu, sv, 8);
            sv += __shfl_xor_sync(0xffffffffu, sv, 16);
            qv += __shfl_xor_sync(0xffffffffu, qv, 4);
            qv += __shfl_xor_sync(0xffffffffu, qv, 8);
            qv += __shfl_xor_sync(0xffffffffu, qv, 16);
            if (lane < 4) {
                int colL = warp_n * 32 + ns * 8 + 2 * lane + par;
                atomicAdd(&sS[colL], sv);
                atomicAdd(&sQ[colL], qv);
            }
        }
    __syncthreads();
    if (tid < 128) {
        atomicAdd(&g_stats[bn + tid], sS[tid]);
        atomicAdd(&g_stats[F1 + bn + tid], sQ[tid]);
    }
}

// prep2: W2h = sc ⊙ W2c (Horner precombine fused), bias2 = sh @ W2c_k (+ b2)
__global__ void prep2_kernel(const float* __restrict__ W2, const float* __restrict__ b2,
                             const float* __restrict__ gamma, const float* __restrict__ beta) {
    int i = blockIdx.x * blockDim.x + threadIdx.x;
    const int SZ = F1 * F2;
    if (i >= SZ) return;
    int ch = i >> 7;
    int j = i & 127;
    float w0 = W2[i], w1 = W2[SZ + i], w2 = W2[2 * SZ + i], w3 = W2[3 * SZ + i];
    float c0 = w0 - w2;
    float c1 = w1 - 3.f * w3;
    float c2 = 2.f * w2;
    float c3 = 4.f * w3;
    float m = g_stats[ch] * (1.f / NN);
    float v = g_stats[F1 + ch] * (1.f / NN) - m * m;
    float inv = rsqrtf(v + 1e-5f);
    float sc = gamma[ch] * inv;
    float sh = beta[ch] - m * sc;
    g_W2h[i]          = __float2half(c0 * sc);
    g_W2h[SZ + i]     = __float2half(c1 * sc);
    g_W2h[2 * SZ + i] = __float2half(c2 * sc);
    g_W2h[3 * SZ + i] = __float2half(c3 * sc);
    atomicAdd(&g_bias2[j],           sh * c0 + ((ch == 0) ? b2[j] : 0.f));
    atomicAdd(&g_bias2[F2 + j],      sh * c1);
    atomicAdd(&g_bias2[2 * F2 + j],  sh * c2);
    atomicAdd(&g_bias2[3 * F2 + j],  sh * c3);
}

// GEMM2: C_k(h) = relu(out1) @ W2h_k + bias2_k ; k = blockIdx.y
__global__ __launch_bounds__(256)
void gemm2_f16(const __half* __restrict__ A) {
    __shared__ __align__(16) __half As[2 * ASTG];
    __shared__ __align__(16) __half Bs[2 * BSTG];

    const int tid = threadIdx.x;
    const int lane = tid & 31;
    const int wid = tid >> 5;
    const int warp_m = wid >> 2;
    const int warp_n = wid & 3;
    const int bm = blockIdx.x * 128;
    const int kblk = blockIdx.y;
    const __half* Wb0 = g_W2h + (size_t)kblk * F1 * F2;
    __half* C = g_Ck + (size_t)kblk * NPAD * F2;
    const int NIT = 8;

    float acc[4][4][4];
#pragma unroll
    for (int i = 0; i < 4; i++)
#pragma unroll
        for (int j = 0; j < 4; j++)
#pragma unroll
            for (int q = 0; q < 4; q++) acc[i][j][q] = 0.f;

    const unsigned asBase0 = (unsigned)__cvta_generic_to_shared(As);
    const unsigned bsBase0 = (unsigned)__cvta_generic_to_shared(Bs);
    const unsigned asFrag = asBase0 +
        ((warp_m * 64 + (lane & 15)) * PA + (lane >> 4) * 8) * 2;
    const int b_k = ((lane >> 3) & 1) * 8 + (lane & 7);
    const int b_n = (lane >> 4) * 8;

    auto load_tiles = [&](int st, int it) {
        int k0 = it * 32;
        const __half* Ab = A + (size_t)bm * F1 + k0;
        const __half* Wb = Wb0 + (size_t)k0 * F2;
        unsigned sA = asBase0 + st * ASTG * 2;
        unsigned sB = bsBase0 + st * BSTG * 2;
#pragma unroll
        for (int p = 0; p < 2; ++p) {
            int idx = p * 256 + tid;
            int rrow = idx >> 2, ch = (idx & 3) * 8;
            cp16(sA + (rrow * PA + ch) * 2, Ab + (size_t)rrow * F1 + ch);
            int kr = idx >> 4, bc = (idx & 15) * 8;
            cp16(sB + (kr * PB + bc) * 2, Wb + (size_t)kr * F2 + bc);
        }
        asm volatile("cp.async.commit_group;");
    };

    load_tiles(0, 0);
    int st = 0;
#pragma unroll 1
    for (int it = 0; it < NIT; ++it) {
        if (it + 1 < NIT) {
            load_tiles(st ^ 1, it + 1);
            asm volatile("cp.async.wait_group 1;");
        } else {
            asm volatile("cp.async.wait_group 0;");
        }
        __syncthreads();
#pragma unroll
        for (int ks = 0; ks < 2; ++ks) {
            unsigned a[4][4];
#pragma unroll
            for (int ms = 0; ms < 4; ++ms) {
                unsigned addr = asFrag + st * ASTG * 2 + ms * (16 * PA * 2) + ks * 32;
                asm volatile(
                    "ldmatrix.sync.aligned.m8n8.x4.shared.b16 {%0,%1,%2,%3}, [%4];"
                    : "=r"(a[ms][0]), "=r"(a[ms][1]), "=r"(a[ms][2]), "=r"(a[ms][3])
                    : "r"(addr));
            }
            unsigned b[4][2];
#pragma unroll
            for (int nsp = 0; nsp < 2; ++nsp) {
                int ncol = warp_n * 32 + nsp * 16 + b_n;
                unsigned baddr = bsBase0 + st * BSTG * 2 +
                                 ((ks * 16 + b_k) * PB + ncol) * 2;
                asm volatile(
                    "ldmatrix.sync.aligned.m8n8.x4.trans.shared.b16 {%0,%1,%2,%3}, [%4];"
                    : "=r"(b[2 * nsp][0]), "=r"(b[2 * nsp][1]),
                      "=r"(b[2 * nsp + 1][0]), "=r"(b[2 * nsp + 1][1])
                    : "r"(baddr));
            }
#pragma unroll
            for (int ms = 0; ms < 4; ++ms)
#pragma unroll
                for (int ns = 0; ns < 4; ++ns) {
                    asm volatile(
                        "mma.sync.aligned.m16n8k16.row.col.f32.f16.f16.f32 "
                        "{%0,%1,%2,%3}, {%4,%5,%6,%7}, {%8,%9}, {%0,%1,%2,%3};"
                        : "+f"(acc[ms][ns][0]), "+f"(acc[ms][ns][1]),
                          "+f"(acc[ms][ns][2]), "+f"(acc[ms][ns][3])
                        : "r"(a[ms][0]), "r"(a[ms][1]), "r"(a[ms][2]), "r"(a[ms][3]),
                          "r"(b[ns][0]), "r"(b[ns][1]));
                }
        }
        __syncthreads();
        st ^= 1;
    }

#pragma unroll
    for (int ms = 0; ms < 4; ++ms) {
        int r0 = bm + warp_m * 64 + ms * 16 + (lane >> 2);
#pragma unroll
        for (int ns = 0; ns < 4; ++ns) {
            int cc = warp_n * 32 + ns * 8 + 2 * (lane & 3);
            float bx = g_bias2[kblk * F2 + cc + 0];
            float by = g_bias2[kblk * F2 + cc + 1];
            __half2 h0 = __floats2half2_rn(acc[ms][ns][0] + bx, acc[ms][ns][1] + by);
            __half2 h1 = __floats2half2_rn(acc[ms][ns][2] + bx, acc[ms][ns][3] + by);
            *(__half2*)&C[(size_t)r0 * F2 + cc] = h0;
            *(__half2*)&C[(size_t)(r0 + 8) * F2 + cc] = h1;
        }
    }
}

// ---------------- BN2 stats ---------------------------------------------------
__global__ void stats_h128(const __half* __restrict__ X) {
    int col = threadIdx.x & 127;
    int ro = threadIdx.x >> 7;
    int r0 = blockIdx.x * 128 + ro;
    int rend = blockIdx.x * 128 + 128;
    if (rend > NN) rend = NN;
    float s = 0.f, s2 = 0.f;
    for (int r = r0; r < rend; r += 2) {
        float v = __half2float(X[(size_t)r * F2 + col]);
        v = v > 0.f ? v : 0.f;
        s += v;
        s2 = fmaf(v, v, s2);
    }
    atomicAdd(&g_stats2[col], s);
    atomicAdd(&g_stats2[F2 + col], s2);
}

// final: out = BN2relu(out2) @ Wlin^T + blin; BN2 fold computed per-block
__global__ void final_kernel(const __half* __restrict__ h,
                             const float* __restrict__ Wl, const float* __restrict__ bl,
                             const float* __restrict__ gamma, const float* __restrict__ beta,
                             float* __restrict__ out) {
    __shared__ float fSc[F2], fSh[F2];
    int tid = threadIdx.x;
    if (tid < F2) {
        float m = g_stats2[tid] * (1.f / NN);
        float v = g_stats2[F2 + tid] * (1.f / NN) - m * m;
        float inv = rsqrtf(v + 1e-5f);
        float sc = gamma[tid] * inv;
        fSc[tid] = sc;
        fSh[tid] = beta[tid] - m * sc;
    }
    __syncthreads();

    int node = (blockIdx.x * blockDim.x + tid) >> 5;
    if (node >= NN) return;
    int lane = tid & 31;
    uint2 u = ((const uint2*)(h + (size_t)node * F2))[lane];
    float2 f0 = __half22float2(*(__half2*)&u.x);
    float2 f1 = __half22float2(*(__half2*)&u.y);
    int c = lane * 4;
    float h0 = fmaf(fmaxf(f0.x, 0.f), fSc[c + 0], fSh[c + 0]);
    float h1 = fmaf(fmaxf(f0.y, 0.f), fSc[c + 1], fSh[c + 1]);
    float h2 = fmaf(fmaxf(f1.x, 0.f), fSc[c + 2], fSh[c + 2]);
    float h3 = fmaf(fmaxf(f1.y, 0.f), fSc[c + 3], fSh[c + 3]);
#pragma unroll
    for (int o = 0; o < 10; ++o) {
        float4 w = ((const float4*)(Wl + o * F2))[lane];
        float p = h0 * w.x + h1 * w.y + h2 * w.z + h3 * w.w;
        p += __shfl_xor_sync(0xffffffffu, p, 16);
        p += __shfl_xor_sync(0xffffffffu, p, 8);
        p += __shfl_xor_sync(0xffffffffu, p, 4);
        p += __shfl_xor_sync(0xffffffffu, p, 2);
        p += __shfl_xor_sync(0xffffffffu, p, 1);
        if (lane == 0) out[node * 10 + o] = p + bl[o];
    }
}

// ---------------- launch ------------------------------------------------------
extern "C" void kernel_launch(void* const* d_in, const int* in_sizes, int n_in,
                              void* d_out, int out_size) {
    const float* x      = (const float*)d_in[0];
    const int*   ei     = (const int*)d_in[1];
    const float* ew     = (const float*)d_in[2];
    const float* W1     = (const float*)d_in[3];
    const float* b1     = (const float*)d_in[4];
    const float* W2     = (const float*)d_in[5];
    const float* b2     = (const float*)d_in[6];
    const float* gamma1 = (const float*)d_in[7];
    const float* beta1  = (const float*)d_in[8];
    const float* gamma2 = (const float*)d_in[9];
    const float* beta2  = (const float*)d_in[10];
    const float* Wlin   = (const float*)d_in[11];
    const float* blin   = (const float*)d_in[12];
    float* out = (float*)d_out;

    const int* row = ei;
    const int* col = ei + EE;

    unsigned* degcnt;
    __half *TxA, *out1, *Ck, *out2;
    cudaGetSymbolAddress((void**)&degcnt, g_degcnt);
    cudaGetSymbolAddress((void**)&TxA,    g_TxA);
    cudaGetSymbolAddress((void**)&out1,   g_out1);
    cudaGetSymbolAddress((void**)&Ck,     g_Ck);
    cudaGetSymbolAddress((void**)&out2,   g_out2);

    const int EB = (EE + 255) / 256;
    const int SB = (NN * 32 + 255) / 256;

    // ---- ELL build ----
    cudaMemsetAsync(degcnt, 0, 2 * NPAD * sizeof(unsigned));
    pass1_kernel<<<EB, 256>>>(row, col, ew);
    transform_kernel<<<SB, 256>>>();
    cvt_kernel<<<(XCNT + WCNT + 255) / 256, 256>>>(x, W1);

    // ---- layer 1: Chebyshev recursion at F=128 (fp16 features) ----
    __half* A0 = TxA;
    __half* A1 = TxA + (size_t)NPAD * F0;
    __half* A2 = TxA + (size_t)2 * NPAD * F0;
    __half* A3 = TxA + (size_t)3 * NPAD * F0;
    spmm_h<<<SB, 256>>>(A0, A1, nullptr, nullptr, 1.f);
    spmm_h<<<SB, 256>>>(A1, A2, A0, nullptr, 2.f);
    spmm_h<<<SB, 256>>>(A2, A3, A1, nullptr, 2.f);

    gemm1_f16<<<dim3(NPAD / 128, 2), 256>>>(TxA, b1, out1);

    // ---- layer 2: Horner form with BN folded into weights ----
    prep2_kernel<<<(F1 * F2 + 255) / 256, 256>>>(W2, b2, gamma1, beta1);
    gemm2_f16<<<dim3(NPAD / 128, 4), 256>>>(out1);

    __half* C0 = Ck;
    __half* C1 = Ck + (size_t)NPAD * F2;
    __half* C2 = Ck + (size_t)2 * NPAD * F2;
    __half* C3 = Ck + (size_t)3 * NPAD * F2;
    __half* t1 = TxA;
    __half* t2 = TxA + (size_t)NPAD * F0;
    spmm_h<<<SB, 256>>>(C3, t1, nullptr, C2, 1.f);
    spmm_h<<<SB, 256>>>(t1, t2, nullptr, C1, 1.f);
    spmm_h<<<SB, 256>>>(t2, out2, nullptr, C0, 1.f);

    stats_h128<<<157, 256>>>(out2);

    final_kernel<<<SB, 256>>>(out2, Wlin, blin, gamma2, beta2, out);
}

// round 16
// speedup vs baseline: 1.2170x; 1.2170x over previous
#include <cuda_runtime.h>
#include <cuda_fp16.h>
#include <cstdint>

// Problem constants
#define NN   20000
#define EE   640000
#define F0   128
#define F1   256
#define F2   128
#define NPAD 20096   // 157 * 128
#define MAXD 128     // ELL slots per node

// ---------------- scratch (device globals, zero at module load) -------------
__device__ __align__(16) unsigned g_degcnt[2 * NPAD];   // deg(float) | cnt(int)
__device__ __align__(16) int2   g_pack[NPAD * MAXD];    // ELL: (src_row, w) per dst
__device__ __align__(16) __half g_TxA[4 * NPAD * F0];
__device__ __align__(16) __half g_out1[NPAD * F1];
__device__ __align__(16) __half g_Ck[4 * NPAD * F2];
__device__ __align__(16) __half g_out2[NPAD * F2];
__device__ __align__(16) __half g_W1h[4 * F0 * F1];
__device__ __align__(16) __half g_W2h[4 * F1 * F2];
__device__ __align__(16) float  g_bias2[4 * F2];
__device__ __align__(16) float  g_stats[2 * F1];
__device__ __align__(16) float  g_stats2[2 * F2];

// ---------------- ELL build: single edge pass --------------------------------
__global__ void pass1_kernel(const int* __restrict__ row,
                             const int* __restrict__ col,
                             const float* __restrict__ ew) {
    int e = blockIdx.x * blockDim.x + threadIdx.x;
    if (e >= EE) return;
    int r = row[e], c = col[e];
    float w = (r == c) ? 0.f : ew[e];
    float* deg = (float*)g_degcnt;
    int*   cnt = (int*)(g_degcnt + NPAD);
    if (w != 0.f) atomicAdd(&deg[r], w);
    int slot = atomicAdd(&cnt[c], 1);
    int2 p;
    p.x = r;
    p.y = __float_as_int(w);
    g_pack[c * MAXD + slot] = p;
}

// transform + converts fused:
//   blocks [0, SBN): wn = -rsqrt(deg[r]) * w * rsqrt(deg[c]) in-place; zero stats
//   blocks [SBN, SBN+CVB): x -> TxA block 0 (fp16), W1 -> W1h (fp16)
#define SBN  ((NN * 32 + 255) / 256)          // 2500 node-transform blocks
#define XCNT (NN * 32)
#define WCNT (4 * F0 * F1 / 4)
#define CVB  ((XCNT + WCNT + 255) / 256)      // convert blocks
__global__ void transform_kernel(const float* __restrict__ x,
                                 const float* __restrict__ W1) {
    int tid = threadIdx.x;
    if (blockIdx.x >= SBN) {
        int i = (blockIdx.x - SBN) * blockDim.x + tid;
        if (i >= XCNT + WCNT) return;
        const float4* src;
        uint2* dst;
        if (i < XCNT) {
            src = (const float4*)x + i;
            dst = (uint2*)g_TxA + i;
        } else {
            src = (const float4*)W1 + (i - XCNT);
            dst = (uint2*)g_W1h + (i - XCNT);
        }
        float4 v = *src;
        uint2 o;
        __half2 h0 = __floats2half2_rn(v.x, v.y);
        __half2 h1 = __floats2half2_rn(v.z, v.w);
        o.x = *(unsigned*)&h0;
        o.y = *(unsigned*)&h1;
        *dst = o;
        return;
    }
    if (blockIdx.x == 0) {
        for (int i = tid; i < 2 * F1; i += 256) g_stats[i] = 0.f;
        for (int i = tid; i < 2 * F2; i += 256) g_stats2[i] = 0.f;
        for (int i = tid; i < 4 * F2; i += 256) g_bias2[i] = 0.f;
    }
    int node = (blockIdx.x * blockDim.x + tid) >> 5;
    if (node >= NN) return;
    int lane = tid & 31;
    const float* deg = (const float*)g_degcnt;
    const int*   cnt = (const int*)(g_degcnt + NPAD);
    float dc = deg[node];
    float disc = (dc > 0.f) ? rsqrtf(dc) : 0.f;
    int n = cnt[node];
    int base = node * MAXD;
    for (int i = lane; i < n; i += 32) {
        int2 p = g_pack[base + i];
        float w = __int_as_float(p.y);
        float dr = deg[p.x];
        float disr = (dr > 0.f) ? rsqrtf(dr) : 0.f;
        p.y = __float_as_int(-disr * w * disc);
        g_pack[base + i] = p;
    }
}

// ---- gather SPMM (fp16, F=128): out = alpha*(L@in) - sub + add --------------
// Converged optimum: shuffles distribute edge metadata, 8 gathers in flight.
__device__ __forceinline__ void hfma4(float4& acc, float w, uint2 u) {
    float2 f0 = __half22float2(*(__half2*)&u.x);
    float2 f1 = __half22float2(*(__half2*)&u.y);
    acc.x = fmaf(w, f0.x, acc.x);
    acc.y = fmaf(w, f0.y, acc.y);
    acc.z = fmaf(w, f1.x, acc.z);
    acc.w = fmaf(w, f1.y, acc.w);
}

__global__ void spmm_h(const __half* __restrict__ in, __half* __restrict__ out,
                       const __half* __restrict__ sub,
                       const __half* __restrict__ add, float alpha) {
    int node = (blockIdx.x * blockDim.x + threadIdx.x) >> 5;
    if (node >= NN) return;
    int lane = threadIdx.x & 31;
    int n = ((const int*)(g_degcnt + NPAD))[node];
    const int2* pk = g_pack + node * MAXD;
    const uint2* base = (const uint2*)in + lane;

    float4 acc0 = make_float4(0.f, 0.f, 0.f, 0.f);
    float4 acc1 = make_float4(0.f, 0.f, 0.f, 0.f);
    float4 acc2 = make_float4(0.f, 0.f, 0.f, 0.f);
    float4 acc3 = make_float4(0.f, 0.f, 0.f, 0.f);

    for (int c0 = 0; c0 < n; c0 += 32) {
        int m = n - c0;
        if (m > 32) m = 32;
        int2 p = (lane < m) ? pk[c0 + lane] : make_int2(0, 0);
        int mm = (m + 7) & ~7;
#pragma unroll 1
        for (int j = 0; j < mm; j += 8) {
            int r0 = __shfl_sync(0xffffffffu, p.x, j + 0);
            int r1 = __shfl_sync(0xffffffffu, p.x, j + 1);
            int r2 = __shfl_sync(0xffffffffu, p.x, j + 2);
            int r3 = __shfl_sync(0xffffffffu, p.x, j + 3);
            int r4 = __shfl_sync(0xffffffffu, p.x, j + 4);
            int r5 = __shfl_sync(0xffffffffu, p.x, j + 5);
            int r6 = __shfl_sync(0xffffffffu, p.x, j + 6);
            int r7 = __shfl_sync(0xffffffffu, p.x, j + 7);
            uint2 u0 = base[(size_t)r0 * 32];
            uint2 u1 = base[(size_t)r1 * 32];
            uint2 u2 = base[(size_t)r2 * 32];
            uint2 u3 = base[(size_t)r3 * 32];
            uint2 u4 = base[(size_t)r4 * 32];
            uint2 u5 = base[(size_t)r5 * 32];
            uint2 u6 = base[(size_t)r6 * 32];
            uint2 u7 = base[(size_t)r7 * 32];
            float w0 = __int_as_float(__shfl_sync(0xffffffffu, p.y, j + 0));
            float w1 = __int_as_float(__shfl_sync(0xffffffffu, p.y, j + 1));
            float w2 = __int_as_float(__shfl_sync(0xffffffffu, p.y, j + 2));
            float w3 = __int_as_float(__shfl_sync(0xffffffffu, p.y, j + 3));
            float w4 = __int_as_float(__shfl_sync(0xffffffffu, p.y, j + 4));
            float w5 = __int_as_float(__shfl_sync(0xffffffffu, p.y, j + 5));
            float w6 = __int_as_float(__shfl_sync(0xffffffffu, p.y, j + 6));
            float w7 = __int_as_float(__shfl_sync(0xffffffffu, p.y, j + 7));
            hfma4(acc0, w0, u0);
            hfma4(acc1, w1, u1);
            hfma4(acc2, w2, u2);
            hfma4(acc3, w3, u3);
            hfma4(acc0, w4, u4);
            hfma4(acc1, w5, u5);
            hfma4(acc2, w6, u6);
            hfma4(acc3, w7, u7);
        }
    }
    float4 r;
    r.x = alpha * ((acc0.x + acc1.x) + (acc2.x + acc3.x));
    r.y = alpha * ((acc0.y + acc1.y) + (acc2.y + acc3.y));
    r.z = alpha * ((acc0.z + acc1.z) + (acc2.z + acc3.z));
    r.w = alpha * ((acc0.w + acc1.w) + (acc2.w + acc3.w));
    size_t oidx = (size_t)node * 32 + lane;
    if (add) {
        uint2 u = ((const uint2*)add)[oidx];
        float2 f0 = __half22float2(*(__half2*)&u.x);
        float2 f1 = __half22float2(*(__half2*)&u.y);
        r.x += f0.x; r.y += f0.y; r.z += f1.x; r.w += f1.y;
    }
    if (sub) {
        uint2 u = ((const uint2*)sub)[oidx];
        float2 f0 = __half22float2(*(__half2*)&u.x);
        float2 f1 = __half22float2(*(__half2*)&u.y);
        r.x -= f0.x; r.y -= f0.y; r.z -= f1.x; r.w -= f1.y;
    }
    uint2 o;
    __half2 h0 = __floats2half2_rn(r.x, r.y);
    __half2 h1 = __floats2half2_rn(r.z, r.w);
    o.x = *(unsigned*)&h0;
    o.y = *(unsigned*)&h1;
    ((uint2*)out)[oidx] = o;
}

// ---------------- fp16 tensor-core GEMMs, cp.async double-buffered -----------
#define PA 40
#define PB 136
#define ASTG (128 * PA)
#define BSTG (32 * PB)

__device__ __forceinline__ void cp16(unsigned sdst, const void* gsrc) {
    asm volatile("cp.async.cg.shared.global [%0], [%1], 16;" :: "r"(sdst), "l"(gsrc));
}

// GEMM1: out1(h) = relu( sum_chunk TxA_chunk @ W1h_chunk + b1 ) ; fused BN1 stats
__global__ __launch_bounds__(256)
void gemm1_f16(const __half* __restrict__ A, const float* __restrict__ bias,
               __half* __restrict__ C) {
    __shared__ __align__(16) __half As[2 * ASTG];
    __shared__ __align__(16) __half Bs[2 * BSTG];
    __shared__ float sS[128], sQ[128];

    const int tid = threadIdx.x;
    const int lane = tid & 31;
    const int wid = tid >> 5;
    const int warp_m = wid >> 2;
    const int warp_n = wid & 3;
    const int bm = blockIdx.x * 128;
    const int bn = blockIdx.y * 128;
    const int NIT = 16;

    if (tid < 128) { sS[tid] = 0.f; sQ[tid] = 0.f; }

    float acc[4][4][4];
#pragma unroll
    for (int i = 0; i < 4; i++)
#pragma unroll
        for (int j = 0; j < 4; j++)
#pragma unroll
            for (int q = 0; q < 4; q++) acc[i][j][q] = 0.f;

    const unsigned asBase0 = (unsigned)__cvta_generic_to_shared(As);
    const unsigned bsBase0 = (unsigned)__cvta_generic_to_shared(Bs);
    const unsigned asFrag = asBase0 +
        ((warp_m * 64 + (lane & 15)) * PA + (lane >> 4) * 8) * 2;
    const int b_k = ((lane >> 3) & 1) * 8 + (lane & 7);
    const int b_n = (lane >> 4) * 8;

    auto load_tiles = [&](int st, int it) {
        int chunk = it >> 2;
        int k0 = (it & 3) * 32;
        const __half* Ab = A + (size_t)chunk * NPAD * F0 + (size_t)bm * F0 + k0;
        const __half* Wb = g_W1h + (size_t)chunk * F0 * F1 + (size_t)k0 * F1 + bn;
        unsigned sA = asBase0 + st * ASTG * 2;
        unsigned sB = bsBase0 + st * BSTG * 2;
#pragma unroll
        for (int p = 0; p < 2; ++p) {
            int idx = p * 256 + tid;
            int rrow = idx >> 2, ch = (idx & 3) * 8;
            cp16(sA + (rrow * PA + ch) * 2, Ab + (size_t)rrow * F0 + ch);
            int kr = idx >> 4, bc = (idx & 15) * 8;
            cp16(sB + (kr * PB + bc) * 2, Wb + (size_t)kr * F1 + bc);
        }
        asm volatile("cp.async.commit_group;");
    };

    load_tiles(0, 0);
    int st = 0;
#pragma unroll 1
    for (int it = 0; it < NIT; ++it) {
        if (it + 1 < NIT) {
            load_tiles(st ^ 1, it + 1);
            asm volatile("cp.async.wait_group 1;");
        } else {
            asm volatile("cp.async.wait_group 0;");
        }
        __syncthreads();
#pragma unroll
        for (int ks = 0; ks < 2; ++ks) {
            unsigned a[4][4];
#pragma unroll
            for (int ms = 0; ms < 4; ++ms) {
                unsigned addr = asFrag + st * ASTG * 2 + ms * (16 * PA * 2) + ks * 32;
                asm volatile(
                    "ldmatrix.sync.aligned.m8n8.x4.shared.b16 {%0,%1,%2,%3}, [%4];"
                    : "=r"(a[ms][0]), "=r"(a[ms][1]), "=r"(a[ms][2]), "=r"(a[ms][3])
                    : "r"(addr));
            }
            unsigned b[4][2];
#pragma unroll
            for (int nsp = 0; nsp < 2; ++nsp) {
                int ncol = warp_n * 32 + nsp * 16 + b_n;
                unsigned baddr = bsBase0 + st * BSTG * 2 +
                                 ((ks * 16 + b_k) * PB + ncol) * 2;
                asm volatile(
                    "ldmatrix.sync.aligned.m8n8.x4.trans.shared.b16 {%0,%1,%2,%3}, [%4];"
                    : "=r"(b[2 * nsp][0]), "=r"(b[2 * nsp][1]),
                      "=r"(b[2 * nsp + 1][0]), "=r"(b[2 * nsp + 1][1])
                    : "r"(baddr));
            }
#pragma unroll
            for (int ms = 0; ms < 4; ++ms)
#pragma unroll
                for (int ns = 0; ns < 4; ++ns) {
                    asm volatile(
                        "mma.sync.aligned.m16n8k16.row.col.f32.f16.f16.f32 "
                        "{%0,%1,%2,%3}, {%4,%5,%6,%7}, {%8,%9}, {%0,%1,%2,%3};"
                        : "+f"(acc[ms][ns][0]), "+f"(acc[ms][ns][1]),
                          "+f"(acc[ms][ns][2]), "+f"(acc[ms][ns][3])
                        : "r"(a[ms][0]), "r"(a[ms][1]), "r"(a[ms][2]), "r"(a[ms][3]),
                          "r"(b[ns][0]), "r"(b[ns][1]));
                }
        }
        __syncthreads();
        st ^= 1;
    }

    float s[4][2], q[4][2];
#pragma unroll
    for (int ns = 0; ns < 4; ++ns) { s[ns][0] = s[ns][1] = q[ns][0] = q[ns][1] = 0.f; }
#pragma unroll
    for (int ms = 0; ms < 4; ++ms) {
        int r0 = bm + warp_m * 64 + ms * 16 + (lane >> 2);
        bool ok0 = r0 < NN, ok1 = (r0 + 8) < NN;
#pragma unroll
        for (int ns = 0; ns < 4; ++ns) {
            int cc = bn + warp_n * 32 + ns * 8 + 2 * (lane & 3);
            float a0 = fmaxf(acc[ms][ns][0] + bias[cc + 0], 0.f);
            float a1 = fmaxf(acc[ms][ns][1] + bias[cc + 1], 0.f);
            float a2 = fmaxf(acc[ms][ns][2] + bias[cc + 0], 0.f);
            float a3 = fmaxf(acc[ms][ns][3] + bias[cc + 1], 0.f);
            __half2 h0 = __floats2half2_rn(a0, a1);
            __half2 h1 = __floats2half2_rn(a2, a3);
            *(__half2*)&C[(size_t)r0 * F1 + cc] = h0;
            *(__half2*)&C[(size_t)(r0 + 8) * F1 + cc] = h1;
            float m0 = ok0 ? a0 : 0.f;
            float m1 = ok0 ? a1 : 0.f;
            float m2 = ok1 ? a2 : 0.f;
            float m3 = ok1 ? a3 : 0.f;
            s[ns][0] += m0 + m2;
            s[ns][1] += m1 + m3;
            q[ns][0] += m0 * m0 + m2 * m2;
            q[ns][1] += m1 * m1 + m3 * m3;
        }
    }
#pragma unroll
    for (int ns = 0; ns < 4; ++ns)
#pragma unroll
        for (int par = 0; par < 2; ++par) {
            float sv = s[ns][par], qv = q[ns][par];
            sv += __shfl_xor_sync(0xffffffffu, sv, 4);
            sv += __shfl_xor_sync(0xffffffffu, sv, 8);
            sv += __shfl_xor_sync(0xffffffffu, sv, 16);
            qv += __shfl_xor_sync(0xffffffffu, qv, 4);
            qv += __shfl_xor_sync(0xffffffffu, qv, 8);
            qv += __shfl_xor_sync(0xffffffffu, qv, 16);
            if (lane < 4) {
                int colL = warp_n * 32 + ns * 8 + 2 * lane + par;
                atomicAdd(&sS[colL], sv);
                atomicAdd(&sQ[colL], qv);
            }
        }
    __syncthreads();
    if (tid < 128) {
        atomicAdd(&g_stats[bn + tid], sS[tid]);
        atomicAdd(&g_stats[F1 + bn + tid], sQ[tid]);
    }
}

// prep2: W2h = sc ⊙ W2c (Horner precombine fused), bias2 = sh @ W2c_k (+ b2)
__global__ void prep2_kernel(const float* __restrict__ W2, const float* __restrict__ b2,
                             const float* __restrict__ gamma, const float* __restrict__ beta) {
    int i = blockIdx.x * blockDim.x + threadIdx.x;
    const int SZ = F1 * F2;
    if (i >= SZ) return;
    int ch = i >> 7;
    int j = i & 127;
    float w0 = W2[i], w1 = W2[SZ + i], w2 = W2[2 * SZ + i], w3 = W2[3 * SZ + i];
    float c0 = w0 - w2;
    float c1 = w1 - 3.f * w3;
    float c2 = 2.f * w2;
    float c3 = 4.f * w3;
    float m = g_stats[ch] * (1.f / NN);
    float v = g_stats[F1 + ch] * (1.f / NN) - m * m;
    float inv = rsqrtf(v + 1e-5f);
    float sc = gamma[ch] * inv;
    float sh = beta[ch] - m * sc;
    g_W2h[i]          = __float2half(c0 * sc);
    g_W2h[SZ + i]     = __float2half(c1 * sc);
    g_W2h[2 * SZ + i] = __float2half(c2 * sc);
    g_W2h[3 * SZ + i] = __float2half(c3 * sc);
    atomicAdd(&g_bias2[j],           sh * c0 + ((ch == 0) ? b2[j] : 0.f));
    atomicAdd(&g_bias2[F2 + j],      sh * c1);
    atomicAdd(&g_bias2[2 * F2 + j],  sh * c2);
    atomicAdd(&g_bias2[3 * F2 + j],  sh * c3);
}

// GEMM2: C_k(h) = relu(out1) @ W2h_k + bias2_k ; k = blockIdx.y
__global__ __launch_bounds__(256)
void gemm2_f16(const __half* __restrict__ A) {
    __shared__ __align__(16) __half As[2 * ASTG];
    __shared__ __align__(16) __half Bs[2 * BSTG];

    const int tid = threadIdx.x;
    const int lane = tid & 31;
    const int wid = tid >> 5;
    const int warp_m = wid >> 2;
    const int warp_n = wid & 3;
    const int bm = blockIdx.x * 128;
    const int kblk = blockIdx.y;
    const __half* Wb0 = g_W2h + (size_t)kblk * F1 * F2;
    __half* C = g_Ck + (size_t)kblk * NPAD * F2;
    const int NIT = 8;

    float acc[4][4][4];
#pragma unroll
    for (int i = 0; i < 4; i++)
#pragma unroll
        for (int j = 0; j < 4; j++)
#pragma unroll
            for (int q = 0; q < 4; q++) acc[i][j][q] = 0.f;

    const unsigned asBase0 = (unsigned)__cvta_generic_to_shared(As);
    const unsigned bsBase0 = (unsigned)__cvta_generic_to_shared(Bs);
    const unsigned asFrag = asBase0 +
        ((warp_m * 64 + (lane & 15)) * PA + (lane >> 4) * 8) * 2;
    const int b_k = ((lane >> 3) & 1) * 8 + (lane & 7);
    const int b_n = (lane >> 4) * 8;

    auto load_tiles = [&](int st, int it) {
        int k0 = it * 32;
        const __half* Ab = A + (size_t)bm * F1 + k0;
        const __half* Wb = Wb0 + (size_t)k0 * F2;
        unsigned sA = asBase0 + st * ASTG * 2;
        unsigned sB = bsBase0 + st * BSTG * 2;
#pragma unroll
        for (int p = 0; p < 2; ++p) {
            int idx = p * 256 + tid;
            int rrow = idx >> 2, ch = (idx & 3) * 8;
            cp16(sA + (rrow * PA + ch) * 2, Ab + (size_t)rrow * F1 + ch);
            int kr = idx >> 4, bc = (idx & 15) * 8;
            cp16(sB + (kr * PB + bc) * 2, Wb + (size_t)kr * F2 + bc);
        }
        asm volatile("cp.async.commit_group;");
    };

    load_tiles(0, 0);
    int st = 0;
#pragma unroll 1
    for (int it = 0; it < NIT; ++it) {
        if (it + 1 < NIT) {
            load_tiles(st ^ 1, it + 1);
            asm volatile("cp.async.wait_group 1;");
        } else {
            asm volatile("cp.async.wait_group 0;");
        }
        __syncthreads();
#pragma unroll
        for (int ks = 0; ks < 2; ++ks) {
            unsigned a[4][4];
#pragma unroll
            for (int ms = 0; ms < 4; ++ms) {
                unsigned addr = asFrag + st * ASTG * 2 + ms * (16 * PA * 2) + ks * 32;
                asm volatile(
                    "ldmatrix.sync.aligned.m8n8.x4.shared.b16 {%0,%1,%2,%3}, [%4];"
                    : "=r"(a[ms][0]), "=r"(a[ms][1]), "=r"(a[ms][2]), "=r"(a[ms][3])
                    : "r"(addr));
            }
            unsigned b[4][2];
#pragma unroll
            for (int nsp = 0; nsp < 2; ++nsp) {
                int ncol = warp_n * 32 + nsp * 16 + b_n;
                unsigned baddr = bsBase0 + st * BSTG * 2 +
                                 ((ks * 16 + b_k) * PB + ncol) * 2;
                asm volatile(
                    "ldmatrix.sync.aligned.m8n8.x4.trans.shared.b16 {%0,%1,%2,%3}, [%4];"
                    : "=r"(b[2 * nsp][0]), "=r"(b[2 * nsp][1]),
                      "=r"(b[2 * nsp + 1][0]), "=r"(b[2 * nsp + 1][1])
                    : "r"(baddr));
            }
#pragma unroll
            for (int ms = 0; ms < 4; ++ms)
#pragma unroll
                for (int ns = 0; ns < 4; ++ns) {
                    asm volatile(
                        "mma.sync.aligned.m16n8k16.row.col.f32.f16.f16.f32 "
                        "{%0,%1,%2,%3}, {%4,%5,%6,%7}, {%8,%9}, {%0,%1,%2,%3};"
                        : "+f"(acc[ms][ns][0]), "+f"(acc[ms][ns][1]),
                          "+f"(acc[ms][ns][2]), "+f"(acc[ms][ns][3])
                        : "r"(a[ms][0]), "r"(a[ms][1]), "r"(a[ms][2]), "r"(a[ms][3]),
                          "r"(b[ns][0]), "r"(b[ns][1]));
                }
        }
        __syncthreads();
        st ^= 1;
    }

#pragma unroll
    for (int ms = 0; ms < 4; ++ms) {
        int r0 = bm + warp_m * 64 + ms * 16 + (lane >> 2);
#pragma unroll
        for (int ns = 0; ns < 4; ++ns) {
            int cc = warp_n * 32 + ns * 8 + 2 * (lane & 3);
            float bx = g_bias2[kblk * F2 + cc + 0];
            float by = g_bias2[kblk * F2 + cc + 1];
            __half2 h0 = __floats2half2_rn(acc[ms][ns][0] + bx, acc[ms][ns][1] + by);
            __half2 h1 = __floats2half2_rn(acc[ms][ns][2] + bx, acc[ms][ns][3] + by);
            *(__half2*)&C[(size_t)r0 * F2 + cc] = h0;
            *(__half2*)&C[(size_t)(r0 + 8) * F2 + cc] = h1;
        }
    }
}

// ---------------- BN2 stats ---------------------------------------------------
__global__ void stats_h128(const __half* __restrict__ X) {
    int col = threadIdx.x & 127;
    int ro = threadIdx.x >> 7;
    int r0 = blockIdx.x * 128 + ro;
    int rend = blockIdx.x * 128 + 128;
    if (rend > NN) rend = NN;
    float s = 0.f, s2 = 0.f;
    for (int r = r0; r < rend; r += 2) {
        float v = __half2float(X[(size_t)r * F2 + col]);
        v = v > 0.f ? v : 0.f;
        s += v;
        s2 = fmaf(v, v, s2);
    }
    atomicAdd(&g_stats2[col], s);
    atomicAdd(&g_stats2[F2 + col], s2);
}

// final: out = BN2relu(out2) @ Wlin^T + blin; BN2 fold computed per-block
__global__ void final_kernel(const __half* __restrict__ h,
                             const float* __restrict__ Wl, const float* __restrict__ bl,
                             const float* __restrict__ gamma, const float* __restrict__ beta,
                             float* __restrict__ out) {
    __shared__ float fSc[F2], fSh[F2];
    int tid = threadIdx.x;
    if (tid < F2) {
        float m = g_stats2[tid] * (1.f / NN);
        float v = g_stats2[F2 + tid] * (1.f / NN) - m * m;
        float inv = rsqrtf(v + 1e-5f);
        float sc = gamma[tid] * inv;
        fSc[tid] = sc;
        fSh[tid] = beta[tid] - m * sc;
    }
    __syncthreads();

    int node = (blockIdx.x * blockDim.x + tid) >> 5;
    if (node >= NN) return;
    int lane = tid & 31;
    uint2 u = ((const uint2*)(h + (size_t)node * F2))[lane];
    float2 f0 = __half22float2(*(__half2*)&u.x);
    float2 f1 = __half22float2(*(__half2*)&u.y);
    int c = lane * 4;
    float h0 = fmaf(fmaxf(f0.x, 0.f), fSc[c + 0], fSh[c + 0]);
    float h1 = fmaf(fmaxf(f0.y, 0.f), fSc[c + 1], fSh[c + 1]);
    float h2 = fmaf(fmaxf(f1.x, 0.f), fSc[c + 2], fSh[c + 2]);
    float h3 = fmaf(fmaxf(f1.y, 0.f), fSc[c + 3], fSh[c + 3]);
#pragma unroll
    for (int o = 0; o < 10; ++o) {
        float4 w = ((const float4*)(Wl + o * F2))[lane];
        float p = h0 * w.x + h1 * w.y + h2 * w.z + h3 * w.w;
        p += __shfl_xor_sync(0xffffffffu, p, 16);
        p += __shfl_xor_sync(0xffffffffu, p, 8);
        p += __shfl_xor_sync(0xffffffffu, p, 4);
        p += __shfl_xor_sync(0xffffffffu, p, 2);
        p += __shfl_xor_sync(0xffffffffu, p, 1);
        if (lane == 0) out[node * 10 + o] = p + bl[o];
    }
}

// ---------------- launch ------------------------------------------------------
extern "C" void kernel_launch(void* const* d_in, const int* in_sizes, int n_in,
                              void* d_out, int out_size) {
    const float* x      = (const float*)d_in[0];
    const int*   ei     = (const int*)d_in[1];
    const float* ew     = (const float*)d_in[2];
    const float* W1     = (const float*)d_in[3];
    const float* b1     = (const float*)d_in[4];
    const float* W2     = (const float*)d_in[5];
    const float* b2     = (const float*)d_in[6];
    const float* gamma1 = (const float*)d_in[7];
    const float* beta1  = (const float*)d_in[8];
    const float* gamma2 = (const float*)d_in[9];
    const float* beta2  = (const float*)d_in[10];
    const float* Wlin   = (const float*)d_in[11];
    const float* blin   = (const float*)d_in[12];
    float* out = (float*)d_out;

    const int* row = ei;
    const int* col = ei + EE;

    unsigned* degcnt;
    __half *TxA, *out1, *Ck, *out2;
    cudaGetSymbolAddress((void**)&degcnt, g_degcnt);
    cudaGetSymbolAddress((void**)&TxA,    g_TxA);
    cudaGetSymbolAddress((void**)&out1,   g_out1);
    cudaGetSymbolAddress((void**)&Ck,     g_Ck);
    cudaGetSymbolAddress((void**)&out2,   g_out2);

    const int EB = (EE + 255) / 256;
    const int SB = SBN;

    // ---- ELL build (+ fused fp16 converts) ----
    cudaMemsetAsync(degcnt, 0, 2 * NPAD * sizeof(unsigned));
    pass1_kernel<<<EB, 256>>>(row, col, ew);
    transform_kernel<<<SB + CVB, 256>>>(x, W1);

    // ---- layer 1: Chebyshev recursion at F=128 (fp16 features) ----
    __half* A0 = TxA;
    __half* A1 = TxA + (size_t)NPAD * F0;
    __half* A2 = TxA + (size_t)2 * NPAD * F0;
    __half* A3 = TxA + (size_t)3 * NPAD * F0;
    spmm_h<<<SB, 256>>>(A0, A1, nullptr, nullptr, 1.f);
    spmm_h<<<SB, 256>>>(A1, A2, A0, nullptr, 2.f);
    spmm_h<<<SB, 256>>>(A2, A3, A1, nullptr, 2.f);

    gemm1_f16<<<dim3(NPAD / 128, 2), 256>>>(TxA, b1, out1);

    // ---- layer 2: Horner form with BN folded into weights ----
    prep2_kernel<<<(F1 * F2 + 255) / 256, 256>>>(W2, b2, gamma1, beta1);
    gemm2_f16<<<dim3(NPAD / 128, 4), 256>>>(out1);

    __half* C0 = Ck;
    __half* C1 = Ck + (size_t)NPAD * F2;
    __half* C2 = Ck + (size_t)2 * NPAD * F2;
    __half* C3 = Ck + (size_t)3 * NPAD * F2;
    __half* t1 = TxA;
    __half* t2 = TxA + (size_t)NPAD * F0;
    spmm_h<<<SB, 256>>>(C3, t1, nullptr, C2, 1.f);
    spmm_h<<<SB, 256>>>(t1, t2, nullptr, C1, 1.f);
    spmm_h<<<SB, 256>>>(t2, out2, nullptr, C0, 1.f);

    stats_h128<<<157, 256>>>(out2);

    final_kernel<<<SB, 256>>>(out2, Wlin, blin, gamma2, beta2, out);
}